// round 1
// baseline (speedup 1.0000x reference)
#include <cuda_runtime.h>
#include <cuda_fp16.h>
#include <cstdint>
#include <cstddef>

// Problem constants (fixed shapes from reference)
#define D_MODEL 1024
#define F_DIM   4096
#define NEXP    8
#define NTOK    8192      // B*S = 4*2048
#define MAXM    8192      // worst-case tokens per expert (each token once/expert)

// GEMM tiling
#define BM  128
#define BN  64
#define BK  32
#define LDA_S (BK + 8)    // padded smem row (halves): 80B stride -> conflict-free ldmatrix

// ---------------- scratch (device globals: allocation-guard safe) --------------
__device__ int   g_counts[NEXP];
__device__ int   g_tokens[NEXP * MAXM];
__device__ float g_gatew[NEXP * MAXM];
__device__ __align__(16) __half g_H[(size_t)NEXP * MAXM * F_DIM];  // expert-ordered hidden acts

// ---------------- PTX helpers ----------------
__device__ __forceinline__ uint32_t smem_u32(const void* p) {
    return (uint32_t)__cvta_generic_to_shared(p);
}
__device__ __forceinline__ void ldm4(uint32_t& r0, uint32_t& r1, uint32_t& r2, uint32_t& r3, uint32_t a) {
    asm volatile("ldmatrix.sync.aligned.m8n8.x4.shared.b16 {%0,%1,%2,%3}, [%4];"
                 : "=r"(r0), "=r"(r1), "=r"(r2), "=r"(r3) : "r"(a));
}
__device__ __forceinline__ void ldm2(uint32_t& r0, uint32_t& r1, uint32_t a) {
    asm volatile("ldmatrix.sync.aligned.m8n8.x2.shared.b16 {%0,%1}, [%2];"
                 : "=r"(r0), "=r"(r1) : "r"(a));
}
__device__ __forceinline__ void mma_16816(float* c, const uint32_t* a, const uint32_t* b) {
    asm volatile("mma.sync.aligned.m16n8k16.row.col.f32.f16.f16.f32 "
                 "{%0,%1,%2,%3}, {%4,%5,%6,%7}, {%8,%9}, {%0,%1,%2,%3};"
                 : "+f"(c[0]), "+f"(c[1]), "+f"(c[2]), "+f"(c[3])
                 : "r"(a[0]), "r"(a[1]), "r"(a[2]), "r"(a[3]), "r"(b[0]), "r"(b[1]));
}

// ---------------- routing ----------------
__global__ void reset_counts_kernel() {
    if (threadIdx.x < NEXP) g_counts[threadIdx.x] = 0;
}

// One warp per token: 8 gate dot-products, top-2, softmax, append to expert lists.
__global__ void gate_kernel(const float* __restrict__ x, const float* __restrict__ gw) {
    const int lane  = threadIdx.x & 31;
    const int token = blockIdx.x * 8 + (threadIdx.x >> 5);
    if (token >= NTOK) return;

    const float* xr = x + (size_t)token * D_MODEL;
    float acc[NEXP];
#pragma unroll
    for (int e = 0; e < NEXP; e++) acc[e] = 0.f;

    for (int d = lane; d < D_MODEL; d += 32) {
        const float xv = xr[d];
#pragma unroll
        for (int e = 0; e < NEXP; e++) acc[e] += xv * __ldg(&gw[e * D_MODEL + d]);
    }
#pragma unroll
    for (int e = 0; e < NEXP; e++) {
#pragma unroll
        for (int off = 16; off > 0; off >>= 1)
            acc[e] += __shfl_xor_sync(0xFFFFFFFFu, acc[e], off);
    }
    if (lane == 0) {
        float v0 = -1e30f, v1 = -1e30f;
        int   i0 = 0,      i1 = 0;
#pragma unroll
        for (int e = 0; e < NEXP; e++) {
            const float v = acc[e];
            if (v > v0)      { v1 = v0; i1 = i0; v0 = v; i0 = e; }
            else if (v > v1) { v1 = v;  i1 = e; }
        }
        const float p0 = 1.f / (1.f + __expf(v1 - v0));  // softmax over {v0,v1}
        const float p1 = 1.f - p0;
        int s0 = atomicAdd(&g_counts[i0], 1);
        g_tokens[i0 * MAXM + s0] = token;
        g_gatew [i0 * MAXM + s0] = p0;
        int s1 = atomicAdd(&g_counts[i1], 1);
        g_tokens[i1 * MAXM + s1] = token;
        g_gatew [i1 * MAXM + s1] = p1;
    }
}

// ---------------- grouped FFN GEMMs ----------------
// SECOND=false: H[r, 0:4096] = relu( X[token(r), :] @ W1[e]^T ),  K = 1024
// SECOND=true : out[token(r), :] += gate_w(r) * ( H[r, :] @ W2[e]^T ), K = 4096
template <bool SECOND>
__global__ __launch_bounds__(256, 2)
void ffn_kernel(const float* __restrict__ x, const float* __restrict__ w,
                float* __restrict__ out) {
    const int e   = blockIdx.z;
    const int cnt = g_counts[e];
    const int m0  = blockIdx.x * BM;
    if (m0 >= cnt) return;
    const int n0   = blockIdx.y * BN;
    const int KDIM = SECOND ? F_DIM : D_MODEL;

    __shared__ __half sA[BM][LDA_S];
    __shared__ __half sB[BN][LDA_S];

    const int tid    = threadIdx.x;
    const int lane   = tid & 31;
    const int wid    = tid >> 5;
    const int warp_m = wid & 3;   // 0..3  -> 32 rows each
    const int warp_n = wid >> 2;  // 0..1  -> 32 cols each

    float acc[2][4][4];
#pragma unroll
    for (int mt = 0; mt < 2; mt++)
#pragma unroll
        for (int nt = 0; nt < 4; nt++)
#pragma unroll
            for (int i = 0; i < 4; i++) acc[mt][nt][i] = 0.f;

    const uint32_t sA_base = smem_u32(&sA[0][0]);
    const uint32_t sB_base = smem_u32(&sB[0][0]);

    const int arow = tid >> 3;        // 0..31
    const int acol = (tid & 7) * 4;   // 0..28 step 4

    // Row gather indices (pass 1) / clamped H rows (pass 2)
    int rowsrc[4];
#pragma unroll
    for (int it = 0; it < 4; it++) {
        int r  = m0 + arow + it * 32;
        int rc = (r < cnt) ? r : (cnt - 1);
        rowsrc[it] = SECOND ? rc : g_tokens[e * MAXM + rc];
    }

    const float* wbase = w + (size_t)e * (size_t)F_DIM * (size_t)D_MODEL;

    for (int k0 = 0; k0 < KDIM; k0 += BK) {
        // ---- load A tile (128 x 32) ----
        if (!SECOND) {
#pragma unroll
            for (int it = 0; it < 4; it++) {
                const float4 v = *(const float4*)(x + (size_t)rowsrc[it] * D_MODEL + k0 + acol);
                __half2* dst = (__half2*)&sA[arow + it * 32][acol];
                dst[0] = __floats2half2_rn(v.x, v.y);
                dst[1] = __floats2half2_rn(v.z, v.w);
            }
        } else {
#pragma unroll
            for (int it = 0; it < 4; it++) {
                const uint2 v = *(const uint2*)(g_H + ((size_t)e * MAXM + rowsrc[it]) * F_DIM + k0 + acol);
                *(uint2*)&sA[arow + it * 32][acol] = v;
            }
        }
        // ---- load B tile (64 x 32), fp32 weights -> fp16 ----
#pragma unroll
        for (int it = 0; it < 2; it++) {
            const int r = arow + it * 32;  // 0..63
            const float4 v = *(const float4*)(wbase + (size_t)(n0 + r) * KDIM + k0 + acol);
            __half2* dst = (__half2*)&sB[r][acol];
            dst[0] = __floats2half2_rn(v.x, v.y);
            dst[1] = __floats2half2_rn(v.z, v.w);
        }
        __syncthreads();

#pragma unroll
        for (int kk = 0; kk < BK; kk += 16) {
            uint32_t afrag[2][4], bfrag[4][2];
#pragma unroll
            for (int mt = 0; mt < 2; mt++) {
                const int row = warp_m * 32 + mt * 16 + (lane & 15);
                const int col = kk + (lane >> 4) * 8;
                ldm4(afrag[mt][0], afrag[mt][1], afrag[mt][2], afrag[mt][3],
                     sA_base + (row * LDA_S + col) * 2);
            }
#pragma unroll
            for (int nt = 0; nt < 4; nt++) {
                const int row = warp_n * 32 + nt * 8 + (lane & 7);
                const int col = kk + ((lane >> 3) & 1) * 8;
                ldm2(bfrag[nt][0], bfrag[nt][1], sB_base + (row * LDA_S + col) * 2);
            }
#pragma unroll
            for (int mt = 0; mt < 2; mt++)
#pragma unroll
                for (int nt = 0; nt < 4; nt++)
                    mma_16816(acc[mt][nt], afrag[mt], bfrag[nt]);
        }
        __syncthreads();
    }

    // ---- epilogue ----
    const int rb = m0 + warp_m * 32 + (lane >> 2);
    const int cb = n0 + warp_n * 32 + (lane & 3) * 2;
    if (!SECOND) {
#pragma unroll
        for (int mt = 0; mt < 2; mt++) {
            const int r0 = rb + mt * 16;
#pragma unroll
            for (int half = 0; half < 2; half++) {       // c0c1 at r, c2c3 at r+8
                const int r = r0 + half * 8;
                if (r < cnt) {
                    __half* hrow = g_H + ((size_t)e * MAXM + r) * F_DIM;
#pragma unroll
                    for (int nt = 0; nt < 4; nt++) {
                        const float v0 = fmaxf(acc[mt][nt][half * 2 + 0], 0.f);
                        const float v1 = fmaxf(acc[mt][nt][half * 2 + 1], 0.f);
                        *(__half2*)&hrow[cb + nt * 8] = __floats2half2_rn(v0, v1);
                    }
                }
            }
        }
    } else {
#pragma unroll
        for (int mt = 0; mt < 2; mt++) {
            const int r0 = rb + mt * 16;
#pragma unroll
            for (int half = 0; half < 2; half++) {
                const int r = r0 + half * 8;
                if (r < cnt) {
                    const int   tok = g_tokens[e * MAXM + r];
                    const float gwv = g_gatew[e * MAXM + r];
                    float* orow = out + (size_t)tok * D_MODEL;
#pragma unroll
                    for (int nt = 0; nt < 4; nt++) {
                        atomicAdd(&orow[cb + nt * 8 + 0], acc[mt][nt][half * 2 + 0] * gwv);
                        atomicAdd(&orow[cb + nt * 8 + 1], acc[mt][nt][half * 2 + 1] * gwv);
                    }
                }
            }
        }
    }
}

// ---------------- launch ----------------
extern "C" void kernel_launch(void* const* d_in, const int* in_sizes, int n_in,
                              void* d_out, int out_size) {
    const float* x   = (const float*)d_in[0];
    const float* gw  = (const float*)d_in[1];
    const float* w1  = (const float*)d_in[2];
    const float* w2  = (const float*)d_in[3];
    float*       out = (float*)d_out;

    reset_counts_kernel<<<1, 32>>>();
    gate_kernel<<<NTOK / 8, 256>>>(x, gw);
    cudaMemsetAsync(d_out, 0, (size_t)out_size * sizeof(float));
    ffn_kernel<false><<<dim3(MAXM / BM, F_DIM / BN, NEXP), 256>>>(x, w1, nullptr);
    ffn_kernel<true ><<<dim3(MAXM / BM, D_MODEL / BN, NEXP), 256>>>(x, w2, out);
}

// round 2
// speedup vs baseline: 2.2897x; 2.2897x over previous
#include <cuda_runtime.h>
#include <cuda_fp16.h>
#include <cstdint>
#include <cstddef>

// Problem constants
#define D_MODEL 1024
#define F_DIM   4096
#define NEXP    8
#define NTOK    8192      // B*S
#define MAXM    8192      // worst-case tokens per expert

// GEMM tiling
#define BM 128
#define BN 128
#define BK 64
#define NSTAGE 3
#define A_ST (BM * BK)          // halves per A stage (8192)
#define B_ST (BN * BK)
#define ST_H (A_ST + B_ST)      // halves per stage (16384 = 32KB)

// ---------------- scratch (device globals) ----------------
__device__ int   g_counts[NEXP];
__device__ int   g_tokens[NEXP * MAXM];
__device__ float g_gatew[NEXP * MAXM];
__device__ __align__(16) __half g_xh [(size_t)NTOK * D_MODEL];
__device__ __align__(16) __half g_w1h[(size_t)NEXP * F_DIM * D_MODEL];
__device__ __align__(16) __half g_w2h[(size_t)NEXP * D_MODEL * F_DIM];
__device__ __align__(16) __half g_H  [(size_t)NEXP * MAXM * F_DIM];

// ---------------- PTX helpers ----------------
__device__ __forceinline__ uint32_t smem_u32(const void* p) {
    return (uint32_t)__cvta_generic_to_shared(p);
}
__device__ __forceinline__ void cp_async16(uint32_t dst, const void* src) {
    asm volatile("cp.async.cg.shared.global [%0], [%1], 16;\n" :: "r"(dst), "l"(src));
}
__device__ __forceinline__ void cp_commit() { asm volatile("cp.async.commit_group;\n"); }
__device__ __forceinline__ void cp_wait1()  { asm volatile("cp.async.wait_group 1;\n"); }
__device__ __forceinline__ void cp_wait0()  { asm volatile("cp.async.wait_group 0;\n"); }

__device__ __forceinline__ void ldm4(uint32_t& r0, uint32_t& r1, uint32_t& r2, uint32_t& r3, uint32_t a) {
    asm volatile("ldmatrix.sync.aligned.m8n8.x4.shared.b16 {%0,%1,%2,%3}, [%4];"
                 : "=r"(r0), "=r"(r1), "=r"(r2), "=r"(r3) : "r"(a));
}
__device__ __forceinline__ void ldm2(uint32_t& r0, uint32_t& r1, uint32_t a) {
    asm volatile("ldmatrix.sync.aligned.m8n8.x2.shared.b16 {%0,%1}, [%2];"
                 : "=r"(r0), "=r"(r1) : "r"(a));
}
__device__ __forceinline__ void mma_16816(float* c, const uint32_t* a, const uint32_t* b) {
    asm volatile("mma.sync.aligned.m16n8k16.row.col.f32.f16.f16.f32 "
                 "{%0,%1,%2,%3}, {%4,%5,%6,%7}, {%8,%9}, {%0,%1,%2,%3};"
                 : "+f"(c[0]), "+f"(c[1]), "+f"(c[2]), "+f"(c[3])
                 : "r"(a[0]), "r"(a[1]), "r"(a[2]), "r"(a[3]), "r"(b[0]), "r"(b[1]));
}

// ---------------- fp32 -> fp16 preconvert ----------------
__global__ void f2h_kernel(const float* __restrict__ src, int sel, int n4) {
    __half* dst = (sel == 0) ? g_xh : (sel == 1) ? g_w1h : g_w2h;
    const int i = blockIdx.x * 256 + threadIdx.x;
    if (i < n4) {
        const float4 v = ((const float4*)src)[i];
        __half2* d2 = (__half2*)dst + 2 * (size_t)i;
        d2[0] = __floats2half2_rn(v.x, v.y);
        d2[1] = __floats2half2_rn(v.z, v.w);
    }
}

// ---------------- routing ----------------
__global__ void reset_counts_kernel() {
    if (threadIdx.x < NEXP) g_counts[threadIdx.x] = 0;
}

__global__ void gate_kernel(const float* __restrict__ x, const float* __restrict__ gw) {
    const int lane  = threadIdx.x & 31;
    const int token = blockIdx.x * 8 + (threadIdx.x >> 5);
    if (token >= NTOK) return;

    const float* xr = x + (size_t)token * D_MODEL;
    float acc[NEXP];
#pragma unroll
    for (int e = 0; e < NEXP; e++) acc[e] = 0.f;
    for (int d = lane; d < D_MODEL; d += 32) {
        const float xv = xr[d];
#pragma unroll
        for (int e = 0; e < NEXP; e++) acc[e] += xv * __ldg(&gw[e * D_MODEL + d]);
    }
#pragma unroll
    for (int e = 0; e < NEXP; e++) {
#pragma unroll
        for (int off = 16; off > 0; off >>= 1)
            acc[e] += __shfl_xor_sync(0xFFFFFFFFu, acc[e], off);
    }
    if (lane == 0) {
        float v0 = -1e30f, v1 = -1e30f;
        int   i0 = 0,      i1 = 0;
#pragma unroll
        for (int e = 0; e < NEXP; e++) {
            const float v = acc[e];
            if (v > v0)      { v1 = v0; i1 = i0; v0 = v; i0 = e; }
            else if (v > v1) { v1 = v;  i1 = e; }
        }
        const float p0 = 1.f / (1.f + __expf(v1 - v0));
        const float p1 = 1.f - p0;
        int s0 = atomicAdd(&g_counts[i0], 1);
        g_tokens[i0 * MAXM + s0] = token;
        g_gatew [i0 * MAXM + s0] = p0;
        int s1 = atomicAdd(&g_counts[i1], 1);
        g_tokens[i1 * MAXM + s1] = token;
        g_gatew [i1 * MAXM + s1] = p1;
    }
}

// ---------------- grouped FFN GEMM, 3-stage cp.async pipeline ----------------
// SECOND=false: H[r,:] = relu(X[tok(r),:] @ W1[e]^T)            K=1024, N=4096
// SECOND=true : out[tok(r),:] += gate(r) * (H[r,:] @ W2[e]^T)    K=4096, N=1024
template <bool SECOND>
__global__ void __launch_bounds__(256) ffn_kernel(float* __restrict__ out) {
    extern __shared__ __half sm[];
    __shared__ const __half* srcA[BM];

    const int e   = blockIdx.z;
    const int cnt = g_counts[e];
    const int m0  = blockIdx.x * BM;
    if (m0 >= cnt) return;
    const int n0  = blockIdx.y * BN;
    constexpr int KDIM = SECOND ? F_DIM : D_MODEL;
    constexpr int KT   = KDIM / BK;

    const int tid    = threadIdx.x;
    const int lane   = tid & 31;
    const int wid    = tid >> 5;
    const int warp_m = wid & 3;   // 4 warps in M (32 rows each)
    const int warp_n = wid >> 2;  // 2 warps in N (64 cols each)

    if (tid < BM) {
        int r = m0 + tid; if (r >= cnt) r = cnt - 1;
        if (!SECOND) srcA[tid] = g_xh + (size_t)g_tokens[e * MAXM + r] * D_MODEL;
        else         srcA[tid] = g_H + ((size_t)e * MAXM + r) * F_DIM;
    }
    __syncthreads();

    const __half* wb = (SECOND ? g_w2h : g_w1h) + (size_t)e * F_DIM * D_MODEL;
    const uint32_t smb = smem_u32(sm);

    auto load_stage = [&](int st, int kt) {
        const int k0 = kt * BK;
        const uint32_t aw = smb + st * (ST_H * 2);
        const uint32_t bw = aw + A_ST * 2;
#pragma unroll
        for (int i = 0; i < 4; i++) {             // A: 128x64 halves, 1024 16B chunks
            const int idx = tid + i * 256;
            const int row = idx >> 3, c = idx & 7;
            cp_async16(aw + (row * BK + ((c ^ (row & 7)) << 3)) * 2, srcA[row] + k0 + c * 8);
        }
#pragma unroll
        for (int i = 0; i < 4; i++) {             // B: 128x64 halves
            const int idx = tid + i * 256;
            const int row = idx >> 3, c = idx & 7;
            cp_async16(bw + (row * BK + ((c ^ (row & 7)) << 3)) * 2,
                       wb + (size_t)(n0 + row) * KDIM + k0 + c * 8);
        }
    };

    float acc[2][8][4] = {};

#pragma unroll
    for (int s = 0; s < NSTAGE - 1; s++) { load_stage(s, s); cp_commit(); }

#pragma unroll 1
    for (int kt = 0; kt < KT; kt++) {
        cp_wait1();
        __syncthreads();          // stage kt ready; all warps done with stage (kt-1)%3

        const int kn = kt + NSTAGE - 1;
        if (kn < KT) load_stage(kn % NSTAGE, kn);
        cp_commit();

        const uint32_t ab = smb + (kt % NSTAGE) * (ST_H * 2);
        const uint32_t bb = ab + A_ST * 2;
#pragma unroll
        for (int kk = 0; kk < BK; kk += 16) {
            uint32_t af[2][4], bf[8][2];
#pragma unroll
            for (int mt = 0; mt < 2; mt++) {
                const int row = warp_m * 32 + mt * 16 + (lane & 15);
                const int col = kk + (lane >> 4) * 8;
                ldm4(af[mt][0], af[mt][1], af[mt][2], af[mt][3],
                     ab + (row * BK + ((((col >> 3)) ^ (row & 7)) << 3)) * 2);
            }
#pragma unroll
            for (int nt = 0; nt < 8; nt++) {
                const int row = warp_n * 64 + nt * 8 + (lane & 7);
                const int col = kk + ((lane >> 3) & 1) * 8;
                ldm2(bf[nt][0], bf[nt][1],
                     bb + (row * BK + ((((col >> 3)) ^ (row & 7)) << 3)) * 2);
            }
#pragma unroll
            for (int mt = 0; mt < 2; mt++)
#pragma unroll
                for (int nt = 0; nt < 8; nt++)
                    mma_16816(acc[mt][nt], af[mt], bf[nt]);
        }
    }
    cp_wait0();

    // ---- epilogue ----
    const int rbase = m0 + warp_m * 32 + (lane >> 2);
    const int cb    = n0 + warp_n * 64 + (lane & 3) * 2;
    if (!SECOND) {
#pragma unroll
        for (int mt = 0; mt < 2; mt++)
#pragma unroll
            for (int half = 0; half < 2; half++) {
                const int r = rbase + mt * 16 + half * 8;
                if (r < cnt) {
                    __half* hrow = g_H + ((size_t)e * MAXM + r) * F_DIM;
#pragma unroll
                    for (int nt = 0; nt < 8; nt++) {
                        const float v0 = fmaxf(acc[mt][nt][half * 2 + 0], 0.f);
                        const float v1 = fmaxf(acc[mt][nt][half * 2 + 1], 0.f);
                        *(__half2*)&hrow[cb + nt * 8] = __floats2half2_rn(v0, v1);
                    }
                }
            }
    } else {
#pragma unroll
        for (int mt = 0; mt < 2; mt++)
#pragma unroll
            for (int half = 0; half < 2; half++) {
                const int r = rbase + mt * 16 + half * 8;
                if (r < cnt) {
                    const int   tok = g_tokens[e * MAXM + r];
                    const float gwv = g_gatew[e * MAXM + r];
                    float* orow = out + (size_t)tok * D_MODEL;
#pragma unroll
                    for (int nt = 0; nt < 8; nt++) {
                        atomicAdd(&orow[cb + nt * 8 + 0], acc[mt][nt][half * 2 + 0] * gwv);
                        atomicAdd(&orow[cb + nt * 8 + 1], acc[mt][nt][half * 2 + 1] * gwv);
                    }
                }
            }
    }
}

// ---------------- launch ----------------
extern "C" void kernel_launch(void* const* d_in, const int* in_sizes, int n_in,
                              void* d_out, int out_size) {
    const float* x   = (const float*)d_in[0];
    const float* gw  = (const float*)d_in[1];
    const float* w1  = (const float*)d_in[2];
    const float* w2  = (const float*)d_in[3];
    float*       out = (float*)d_out;

    const int smem_bytes = NSTAGE * ST_H * (int)sizeof(__half);   // 96 KB
    cudaFuncSetAttribute(ffn_kernel<false>, cudaFuncAttributeMaxDynamicSharedMemorySize, smem_bytes);
    cudaFuncSetAttribute(ffn_kernel<true>,  cudaFuncAttributeMaxDynamicSharedMemorySize, smem_bytes);

    // fp32 -> fp16 preconversion
    const int nx4 = NTOK * D_MODEL / 4;                  // 2,097,152
    const int nw4 = NEXP * F_DIM * D_MODEL / 4;          // 8,388,608
    f2h_kernel<<<(nx4 + 255) / 256, 256>>>(x,  0, nx4);
    f2h_kernel<<<(nw4 + 255) / 256, 256>>>(w1, 1, nw4);
    f2h_kernel<<<(nw4 + 255) / 256, 256>>>(w2, 2, nw4);

    reset_counts_kernel<<<1, 32>>>();
    gate_kernel<<<NTOK / 8, 256>>>(x, gw);
    cudaMemsetAsync(d_out, 0, (size_t)out_size * sizeof(float));

    ffn_kernel<false><<<dim3(MAXM / BM, F_DIM / BN, NEXP), 256, smem_bytes>>>(nullptr);
    ffn_kernel<true ><<<dim3(MAXM / BM, D_MODEL / BN, NEXP), 256, smem_bytes>>>(out);
}

// round 4
// speedup vs baseline: 2.3601x; 1.0307x over previous
#include <cuda_runtime.h>
#include <cuda_fp16.h>
#include <cstdint>
#include <cstddef>

// Problem constants
#define D_MODEL 1024
#define F_DIM   4096
#define NEXP    8
#define NTOK    8192
#define MAXM    8192

// GEMM tiling: CTA 128x128x64, 4 warps (2x2), warp tile 64x64, 3-stage cp.async
#define BM 128
#define BN 128
#define BK 64
#define NST 3
#define A_BYTES (BM * BK * 2)        // 16384
#define B_BYTES (BN * BK * 2)        // 16384
#define STG_B   (A_BYTES + B_BYTES)  // 32768
#define SMEM_REQ (NST * STG_B)       // 98304

// ---------------- scratch (device globals) ----------------
__device__ int   g_counts[NEXP];
__device__ int   g_tokens[NEXP * MAXM];
__device__ float g_gatew[NEXP * MAXM];
__device__ __align__(16) __half g_xh [(size_t)NTOK * D_MODEL];
__device__ __align__(16) __half g_w1h[(size_t)NEXP * F_DIM * D_MODEL];
__device__ __align__(16) __half g_w2h[(size_t)NEXP * D_MODEL * F_DIM];
__device__ __align__(16) __half g_H  [(size_t)NEXP * MAXM * F_DIM];

// ---------------- PTX helpers ----------------
__device__ __forceinline__ uint32_t smem_u32(const void* p) {
    return (uint32_t)__cvta_generic_to_shared(p);
}
__device__ __forceinline__ void cp_async16(uint32_t dst, const void* src) {
    asm volatile("cp.async.cg.shared.global [%0], [%1], 16;\n" :: "r"(dst), "l"(src));
}
__device__ __forceinline__ void cp_commit() { asm volatile("cp.async.commit_group;\n"); }
__device__ __forceinline__ void cp_wait1()  { asm volatile("cp.async.wait_group 1;\n"); }

__device__ __forceinline__ void ldm4(uint32_t& r0, uint32_t& r1, uint32_t& r2, uint32_t& r3, uint32_t a) {
    asm volatile("ldmatrix.sync.aligned.m8n8.x4.shared.b16 {%0,%1,%2,%3}, [%4];"
                 : "=r"(r0), "=r"(r1), "=r"(r2), "=r"(r3) : "r"(a));
}
__device__ __forceinline__ void mma_16816(float* c, const uint32_t* a, const uint32_t* b) {
    asm volatile("mma.sync.aligned.m16n8k16.row.col.f32.f16.f16.f32 "
                 "{%0,%1,%2,%3}, {%4,%5,%6,%7}, {%8,%9}, {%0,%1,%2,%3};"
                 : "+f"(c[0]), "+f"(c[1]), "+f"(c[2]), "+f"(c[3])
                 : "r"(a[0]), "r"(a[1]), "r"(a[2]), "r"(a[3]), "r"(b[0]), "r"(b[1]));
}

// ---------------- fp32 -> fp16 preconvert ----------------
__global__ void f2h_kernel(const float* __restrict__ src, int sel, int n4) {
    __half* dst = (sel == 0) ? g_xh : (sel == 1) ? g_w1h : g_w2h;
    const int i = blockIdx.x * 256 + threadIdx.x;
    if (i < n4) {
        const float4 v = ((const float4*)src)[i];
        __half2* d2 = (__half2*)dst + 2 * (size_t)i;
        d2[0] = __floats2half2_rn(v.x, v.y);
        d2[1] = __floats2half2_rn(v.z, v.w);
    }
}

// ---------------- routing ----------------
__global__ void reset_counts_kernel() {
    if (threadIdx.x < NEXP) g_counts[threadIdx.x] = 0;
}

__global__ void gate_kernel(const float* __restrict__ x, const float* __restrict__ gw) {
    const int lane  = threadIdx.x & 31;
    const int token = blockIdx.x * 8 + (threadIdx.x >> 5);
    if (token >= NTOK) return;

    const float* xr = x + (size_t)token * D_MODEL;
    float acc[NEXP];
#pragma unroll
    for (int e = 0; e < NEXP; e++) acc[e] = 0.f;
    for (int d = lane; d < D_MODEL; d += 32) {
        const float xv = xr[d];
#pragma unroll
        for (int e = 0; e < NEXP; e++) acc[e] += xv * __ldg(&gw[e * D_MODEL + d]);
    }
#pragma unroll
    for (int e = 0; e < NEXP; e++) {
#pragma unroll
        for (int off = 16; off > 0; off >>= 1)
            acc[e] += __shfl_xor_sync(0xFFFFFFFFu, acc[e], off);
    }
    if (lane == 0) {
        float v0 = -1e30f, v1 = -1e30f;
        int   i0 = 0,      i1 = 0;
#pragma unroll
        for (int e = 0; e < NEXP; e++) {
            const float v = acc[e];
            if (v > v0)      { v1 = v0; i1 = i0; v0 = v; i0 = e; }
            else if (v > v1) { v1 = v;  i1 = e; }
        }
        const float p0 = 1.f / (1.f + __expf(v1 - v0));
        const float p1 = 1.f - p0;
        int s0 = atomicAdd(&g_counts[i0], 1);
        g_tokens[i0 * MAXM + s0] = token;
        g_gatew [i0 * MAXM + s0] = p0;
        int s1 = atomicAdd(&g_counts[i1], 1);
        g_tokens[i1 * MAXM + s1] = token;
        g_gatew [i1 * MAXM + s1] = p1;
    }
}

// ---------------- grouped FFN GEMM ----------------
// SECOND=false: H[r,:] = relu(X[tok(r),:] @ W1[e]^T)          K=1024, N=4096
// SECOND=true : out[tok(r),:] += gate(r)*(H[r,:] @ W2[e]^T)   K=4096, N=1024
template <bool SECOND>
__global__ void __launch_bounds__(128, 2) ffn_kernel(float* __restrict__ out) {
    extern __shared__ __align__(128) char sm[];
    __shared__ const __half* srcA[BM];

    const int e   = blockIdx.z;
    const int cnt = g_counts[e];
    const int m0  = blockIdx.x * BM;
    if (m0 >= cnt) return;
    const int n0  = blockIdx.y * BN;
    constexpr int KDIM = SECOND ? F_DIM : D_MODEL;
    constexpr int KT   = KDIM / BK;

    const int tid    = threadIdx.x;
    const int lane   = tid & 31;
    const int wid    = tid >> 5;
    const int warp_m = wid & 1;        // 2 warps in M (64 rows each)
    const int warp_n = (wid >> 1) & 1; // 2 warps in N (64 cols each)

    {
        int r = m0 + tid; if (r >= cnt) r = cnt - 1;
        srcA[tid] = SECOND ? g_H + ((size_t)e * MAXM + r) * F_DIM
                           : g_xh + (size_t)g_tokens[e * MAXM + r] * D_MODEL;
    }
    __syncthreads();

    const __half*  wb  = (SECOND ? g_w2h : g_w1h) + (size_t)e * F_DIM * D_MODEL;
    const uint32_t smb = smem_u32(sm);

    auto load_stage = [&](int st, int kt) {
        const uint32_t aw = smb + st * STG_B;
        const uint32_t bw = aw + A_BYTES;
        const int k0 = kt * BK;
#pragma unroll
        for (int i = 0; i < 8; i++) {                   // A: 1024 16B chunks / 128 thr
            const int idx = tid + i * 128;
            const int row = idx >> 3, c = idx & 7;
            cp_async16(aw + row * 128 + ((c ^ (row & 7)) << 4), srcA[row] + k0 + c * 8);
        }
#pragma unroll
        for (int i = 0; i < 8; i++) {                   // B: 1024 16B chunks
            const int idx = tid + i * 128;
            const int row = idx >> 3, c = idx & 7;
            cp_async16(bw + row * 128 + ((c ^ (row & 7)) << 4),
                       wb + (size_t)(n0 + row) * KDIM + k0 + c * 8);
        }
    };

    float acc[4][8][4] = {};

    load_stage(0, 0); cp_commit();
    load_stage(1, 1); cp_commit();

#pragma unroll 1
    for (int kt = 0; kt < KT; kt++) {
        cp_wait1();              // stage kt landed (only stage kt+1 may be pending)
        __syncthreads();         // visible to all; all warps done reading slot (kt-1)%3

        const int kn = kt + 2;
        if (kn < KT) load_stage(kn % NST, kn);   // refill slot (kt-1)%3
        cp_commit();

        const uint32_t ab = smb + (kt % NST) * STG_B;
        const uint32_t bb = ab + A_BYTES;
#pragma unroll
        for (int kk8 = 0; kk8 < 8; kk8 += 2) {   // k16 steps
            uint32_t af[4][4], bf[8][2];
#pragma unroll
            for (int mt = 0; mt < 4; mt++) {
                const int row = warp_m * 64 + mt * 16 + (lane & 15);
                const int k8  = kk8 + (lane >> 4);
                ldm4(af[mt][0], af[mt][1], af[mt][2], af[mt][3],
                     ab + row * 128 + ((k8 ^ (row & 7)) << 4));
            }
#pragma unroll
            for (int i = 0; i < 4; i++) {        // each ldm4 -> two n8k16 B frags
                const int row = warp_n * 64 + i * 16 + ((lane >> 4) << 3) + (lane & 7);
                const int k8  = kk8 + ((lane >> 3) & 1);
                ldm4(bf[2 * i][0], bf[2 * i][1], bf[2 * i + 1][0], bf[2 * i + 1][1],
                     bb + row * 128 + ((k8 ^ (row & 7)) << 4));
            }
#pragma unroll
            for (int mt = 0; mt < 4; mt++)
#pragma unroll
                for (int nt = 0; nt < 8; nt++)
                    mma_16816(acc[mt][nt], af[mt], bf[nt]);
        }
    }

    // ---- epilogue ----
    const int rbase = m0 + warp_m * 64 + (lane >> 2);
    const int cb    = n0 + warp_n * 64 + (lane & 3) * 2;
    if (!SECOND) {
#pragma unroll
        for (int mt = 0; mt < 4; mt++)
#pragma unroll
            for (int half = 0; half < 2; half++) {
                const int r = rbase + mt * 16 + half * 8;
                if (r < cnt) {
                    __half* hrow = g_H + ((size_t)e * MAXM + r) * F_DIM;
#pragma unroll
                    for (int nt = 0; nt < 8; nt++) {
                        const float v0 = fmaxf(acc[mt][nt][half * 2 + 0], 0.f);
                        const float v1 = fmaxf(acc[mt][nt][half * 2 + 1], 0.f);
                        *(__half2*)&hrow[cb + nt * 8] = __floats2half2_rn(v0, v1);
                    }
                }
            }
    } else {
#pragma unroll
        for (int mt = 0; mt < 4; mt++)
#pragma unroll
            for (int half = 0; half < 2; half++) {
                const int r = rbase + mt * 16 + half * 8;
                if (r < cnt) {
                    const int   tok = g_tokens[e * MAXM + r];
                    const float gwv = g_gatew[e * MAXM + r];
                    float* orow = out + (size_t)tok * D_MODEL;
#pragma unroll
                    for (int nt = 0; nt < 8; nt++) {
                        atomicAdd(&orow[cb + nt * 8 + 0], acc[mt][nt][half * 2 + 0] * gwv);
                        atomicAdd(&orow[cb + nt * 8 + 1], acc[mt][nt][half * 2 + 1] * gwv);
                    }
                }
            }
    }
}

// ---------------- launch ----------------
extern "C" void kernel_launch(void* const* d_in, const int* in_sizes, int n_in,
                              void* d_out, int out_size) {
    const float* x   = (const float*)d_in[0];
    const float* gw  = (const float*)d_in[1];
    const float* w1  = (const float*)d_in[2];
    const float* w2  = (const float*)d_in[3];
    float*       out = (float*)d_out;

    cudaFuncSetAttribute(ffn_kernel<false>, cudaFuncAttributeMaxDynamicSharedMemorySize, SMEM_REQ);
    cudaFuncSetAttribute(ffn_kernel<true>,  cudaFuncAttributeMaxDynamicSharedMemorySize, SMEM_REQ);

    const int nx4 = NTOK * D_MODEL / 4;
    const int nw4 = NEXP * F_DIM * D_MODEL / 4;
    f2h_kernel<<<(nx4 + 255) / 256, 256>>>(x,  0, nx4);
    f2h_kernel<<<(nw4 + 255) / 256, 256>>>(w1, 1, nw4);
    f2h_kernel<<<(nw4 + 255) / 256, 256>>>(w2, 2, nw4);

    reset_counts_kernel<<<1, 32>>>();
    gate_kernel<<<NTOK / 8, 256>>>(x, gw);
    cudaMemsetAsync(d_out, 0, (size_t)out_size * sizeof(float));

    ffn_kernel<false><<<dim3(MAXM / BM, F_DIM / BN, NEXP), 128, SMEM_REQ>>>(nullptr);
    ffn_kernel<true ><<<dim3(MAXM / BM, D_MODEL / BN, NEXP), 128, SMEM_REQ>>>(out);
}